// round 6
// baseline (speedup 1.0000x reference)
#include <cuda_runtime.h>
#include <cstdint>

#define Bn 16
#define Vn 40000
#define Cn 128
#define Hn 56
#define Wn 56
#define En 120000
#define Mn (Bn*Vn)          // 640000
#define HWn (Hn*Wn)         // 3136
#define CHUNK_B 2
#define CHUNK_ROWS (CHUNK_B*Vn)        // 80000
#define NCHUNKS (Bn/CHUNK_B)           // 8
#define CTILES (CHUNK_ROWS/32)         // 2500

// ---------------- device scratch ----------------
__device__ float g_imgT[(size_t)Bn*HWn*Cn];     // [B,H,W,C]
__device__ float g_A [81920000];                // G, later U (tf32-rounded)
__device__ float g_Dk[81920000];                // D (tf32-rounded; residual)
__device__ float g_S [81920000];                // S = A*X (tf32-rounded)
__device__ float g_Bt[6*128*128];               // transposed tf32 weights [n][k]

__device__ int g_deg[Vn];
__device__ int g_cursor[Vn];
__device__ int g_rowptr[Vn+1];
__device__ int g_col[2*En];

// ---------------- helpers ----------------
__device__ __forceinline__ float rnd_tf32(float x) {
    float r;
    asm("cvt.rna.tf32.f32 %0, %1;" : "=f"(r) : "f"(x));
    return r;
}

__device__ __forceinline__ uint32_t smem_u32(const void* p) {
    uint32_t a;
    asm("{ .reg .u64 t; cvta.to.shared.u64 t, %1; cvt.u32.u64 %0, t; }" : "=r"(a) : "l"(p));
    return a;
}

__device__ __forceinline__ void mma_tf32(float* c, const uint32_t* a, const uint32_t* b) {
    asm volatile(
        "mma.sync.aligned.m16n8k8.row.col.f32.tf32.tf32.f32 "
        "{%0,%1,%2,%3}, {%4,%5,%6,%7}, {%8,%9}, {%0,%1,%2,%3};"
        : "+f"(c[0]), "+f"(c[1]), "+f"(c[2]), "+f"(c[3])
        : "r"(a[0]), "r"(a[1]), "r"(a[2]), "r"(a[3]), "r"(b[0]), "r"(b[1]));
}

// ---------------- CSR build ----------------
__global__ void zero_csr() {
    int i = blockIdx.x*blockDim.x + threadIdx.x;
    if (i < Vn) { g_deg[i] = 0; g_cursor[i] = 0; }
}

__global__ void count_edges(const int* __restrict__ edges) {
    int e = blockIdx.x*blockDim.x + threadIdx.x;
    if (e < En) {
        atomicAdd(&g_deg[edges[2*e+0]], 1);
        atomicAdd(&g_deg[edges[2*e+1]], 1);
    }
}

__global__ void scan_kernel() {
    __shared__ int partial[1024];
    int t = threadIdx.x;
    const int CH = (Vn + 1023) / 1024;
    int base = t * CH;
    int s = 0;
    for (int i = 0; i < CH; i++) {
        int idx = base + i;
        if (idx < Vn) s += g_deg[idx];
    }
    partial[t] = s;
    __syncthreads();
    for (int off = 1; off < 1024; off <<= 1) {
        int v = 0;
        if (t >= off) v = partial[t - off];
        __syncthreads();
        partial[t] += v;
        __syncthreads();
    }
    int run = (t == 0) ? 0 : partial[t-1];
    for (int i = 0; i < CH; i++) {
        int idx = base + i;
        if (idx < Vn) { g_rowptr[idx] = run; run += g_deg[idx]; }
    }
    if (t == 1023) g_rowptr[Vn] = run;
}

__global__ void fill_edges(const int* __restrict__ edges) {
    int e = blockIdx.x*blockDim.x + threadIdx.x;
    if (e < En) {
        int i = edges[2*e+0], j = edges[2*e+1];
        int p = atomicAdd(&g_cursor[i], 1);
        g_col[g_rowptr[i] + p] = j;
        int q = atomicAdd(&g_cursor[j], 1);
        g_col[g_rowptr[j] + q] = i;
    }
}

// ---------------- weight prep: all 6 matrices in one launch ----------------
// Bt[m][n*128+k] = round_tf32(W_m[k*128+n])
__global__ void prep_weights_all(const float* __restrict__ W0_1, const float* __restrict__ W1_1,
                                 const float* __restrict__ W0_2, const float* __restrict__ W1_2,
                                 const float* __restrict__ W0_3, const float* __restrict__ W1_3,
                                 float* __restrict__ Bt) {
    int i = blockIdx.x*blockDim.x + threadIdx.x;   // 6*16384
    int m = i >> 14;
    int r = i & 16383;
    int n = r >> 7, k = r & 127;
    const float* W = (m == 0) ? W0_1 : (m == 1) ? W1_1 : (m == 2) ? W0_2 :
                     (m == 3) ? W1_2 : (m == 4) ? W0_3 : W1_3;
    Bt[i] = rnd_tf32(W[k*128 + n]);
}

// ---------------- image transpose [B,C,H,W] -> [B,H,W,C] ----------------
__global__ void transpose_img(const float* __restrict__ img) {
    __shared__ float tile[32][33];
    int b   = blockIdx.z;
    int hw0 = blockIdx.x * 32;
    int c0  = blockIdx.y * 32;
    int tx = threadIdx.x, ty = threadIdx.y;
    int hw = hw0 + tx, c = c0 + ty;
    if (hw < HWn)
        tile[ty][tx] = img[((size_t)(b*Cn + c))*HWn + hw];
    __syncthreads();
    int hw2 = hw0 + ty, c2 = c0 + tx;
    if (hw2 < HWn)
        g_imgT[((size_t)(b*HWn + hw2))*Cn + c2] = tile[tx][ty];
}

// ---------------- vert_align + add padded -> g_A (tf32-rounded) ----------------
__global__ void vert_align_kernel(const float* __restrict__ vpos,
                                  const float* __restrict__ vpad) {
    int gw   = (blockIdx.x*blockDim.x + threadIdx.x) >> 5;
    int lane = threadIdx.x & 31;
    if (gw >= Mn) return;
    int b = gw / Vn;

    float px = vpos[(size_t)gw*3 + 0];
    float py = vpos[(size_t)gw*3 + 1];
    float x = (px + 1.0f) * 0.5f * (float)(Wn - 1);
    float y = (py + 1.0f) * 0.5f * (float)(Hn - 1);
    float x0f = floorf(x), y0f = floorf(y);
    float wx1 = x - x0f, wx0 = 1.0f - wx1;
    float wy1 = y - y0f, wy0 = 1.0f - wy1;
    int x0 = (int)x0f, y0 = (int)y0f;

    float4 acc = ((const float4*)(vpad + (size_t)gw*Cn))[lane];

    int   xs_[4] = { x0, x0+1, x0,   x0+1 };
    int   ys_[4] = { y0, y0,   y0+1, y0+1 };
    float ws_[4] = { wx0*wy0, wx1*wy0, wx0*wy1, wx1*wy1 };

    #pragma unroll
    for (int t = 0; t < 4; t++) {
        int xi = xs_[t], yi = ys_[t];
        bool inb = (xi >= 0) && (xi < Wn) && (yi >= 0) && (yi < Hn);
        float wgt = inb ? ws_[t] : 0.0f;
        if (wgt != 0.0f) {
            float4 f = ((const float4*)(g_imgT + ((size_t)((b*Hn + yi)*Wn + xi))*Cn))[lane];
            acc.x += wgt*f.x; acc.y += wgt*f.y; acc.z += wgt*f.z; acc.w += wgt*f.w;
        }
    }
    acc.x = rnd_tf32(acc.x); acc.y = rnd_tf32(acc.y);
    acc.z = rnd_tf32(acc.z); acc.w = rnd_tf32(acc.w);
    ((float4*)(g_A + (size_t)gw*Cn))[lane] = acc;
}

// ---------------- agg (chunked): S[row] = rnd( sum_{j in N(v)} X[b,j] ) ----------------
__global__ void agg_kernel(const float* __restrict__ X, float* __restrict__ S, int row0) {
    int gw   = row0 + ((blockIdx.x*blockDim.x + threadIdx.x) >> 5);
    int lane = threadIdx.x & 31;
    int b = gw / Vn;
    int v = gw - b*Vn;

    const float* Xb = X + (size_t)b*Vn*Cn + lane*4;
    float4 acc = make_float4(0,0,0,0);
    int s = g_rowptr[v];
    int e = g_rowptr[v+1];
    for (int p = s; p < e; p++) {
        int j = __ldg(&g_col[p]);
        float4 t = *(const float4*)(Xb + (size_t)j*Cn);
        acc.x += t.x; acc.y += t.y; acc.z += t.z; acc.w += t.w;
    }
    acc.x = rnd_tf32(acc.x); acc.y = rnd_tf32(acc.y);
    acc.z = rnd_tf32(acc.z); acc.w = rnd_tf32(acc.w);
    *(float4*)(S + (size_t)gw*Cn + lane*4) = acc;
}

// ---------------- fused conv GEMM: Y = [X|S](32x256) @ Wcat^T(256x128) + b0 (+Dadd) ----------------
// SMEM floats: sB[128n x 256k] swz | sA[2][32 x 256] swz | sRed[4][32][34] | sbias[128]
#define SB_OFF    0
#define SA_OFF    32768
#define SRED_OFF  49152
#define SBIAS_OFF 53504
#define SMEM_FLOATS 53632      // 214528 B

__device__ __forceinline__ void issue_xs(const float* __restrict__ X,
                                         const float* __restrict__ S,
                                         int t, int buf, int tid, uint32_t sA_u) {
    size_t rb = (size_t)t * 32;
    uint32_t dbase = sA_u + (uint32_t)buf * 32768u;   // bytes (8192 floats per stage)
    #pragma unroll
    for (int j = 0; j < 4; j++) {
        int i4 = tid + j*256;                // 0..1023
        int row = i4 >> 5;                   // 0..31
        int kq  = (i4 & 31) << 2;            // 0..124
        uint32_t off = (uint32_t)((row << 8) + (kq ^ ((row & 7) << 2))) * 4u;
        asm volatile("cp.async.cg.shared.global [%0], [%1], 16;"
            :: "r"(dbase + off), "l"(X + (rb + row)*128 + kq));
    }
    #pragma unroll
    for (int j = 0; j < 4; j++) {
        int i4 = tid + j*256;
        int row = i4 >> 5;
        int kq  = (i4 & 31) << 2;
        uint32_t off = (uint32_t)((row << 8) + ((128 + kq) ^ ((row & 7) << 2))) * 4u;
        asm volatile("cp.async.cg.shared.global [%0], [%1], 16;"
            :: "r"(dbase + off), "l"(S + (rb + row)*128 + kq));
    }
    asm volatile("cp.async.commit_group;" ::: "memory");
}

__global__ void __launch_bounds__(256, 1)
gconv_gemm(const float* __restrict__ X, const float* __restrict__ S,
           const float* __restrict__ Bt0, const float* __restrict__ Bt1,
           const float* __restrict__ bias,
           const float* __restrict__ Dadd,
           float* __restrict__ Y,
           int do_round, int tile0, int tile_end) {
    extern __shared__ float smf[];
    float* sB    = smf + SB_OFF;
    float* sA    = smf + SA_OFF;
    float* sRed  = smf + SRED_OFF;
    float* sbias = smf + SBIAS_OFF;

    int tid = threadIdx.x;
    int wid = tid >> 5, lane = tid & 31;
    int gidx = lane >> 2, tig = lane & 3;
    int kh = wid >> 2;          // k-half: 0 -> k[0,128)=W0 path, 1 -> k[128,256)=W1 path
    int ng = wid & 3;           // col group: 32 cols each

    // weights: sB[n][k]: k<128 = W0t, k>=128 = W1t
    for (int i4 = tid; i4 < 8192; i4 += 256) {
        int n  = i4 >> 6;
        int kq = (i4 & 63) << 2;
        float4 v = (kq < 128) ? *(const float4*)(Bt0 + n*128 + kq)
                              : *(const float4*)(Bt1 + n*128 + (kq - 128));
        *(float4*)(sB + n*256 + (kq ^ ((n & 7) << 2))) = v;
    }
    if (tid < 128) sbias[tid] = bias[tid];

    uint32_t sA_u = smem_u32(sA);
    const int grid = gridDim.x;

    int t0 = tile0 + blockIdx.x;
    if (t0 < tile_end) issue_xs(X, S, t0, 0, tid, sA_u);

    int it = 0;
    for (int t = t0; t < tile_end; t += grid, it++) {
        int tn = t + grid;
        if (tn < tile_end) {
            issue_xs(X, S, tn, (it + 1) & 1, tid, sA_u);
            asm volatile("cp.async.wait_group 1;" ::: "memory");
        } else {
            asm volatile("cp.async.wait_group 0;" ::: "memory");
        }
        __syncthreads();   // cur stage visible; prev iter epilogue done (sRed free)

        const float* sAc = sA + (it & 1) * 8192;

        float c[2][4][4];
        #pragma unroll
        for (int mt = 0; mt < 2; mt++)
            #pragma unroll
            for (int nt = 0; nt < 4; nt++)
                #pragma unroll
                for (int q = 0; q < 4; q++) c[mt][nt][q] = 0.0f;

        const int kb0 = kh * 128;
        #pragma unroll 4
        for (int ks = 0; ks < 16; ks++) {
            int kb = kb0 + ks*8;
            uint32_t a[2][4];
            #pragma unroll
            for (int mt = 0; mt < 2; mt++) {
                int r0 = mt*16 + gidx;
                int sw = (r0 & 7) << 2;
                a[mt][0] = __float_as_uint(sAc[r0*256     + ((kb+tig)   ^ sw)]);
                a[mt][1] = __float_as_uint(sAc[(r0+8)*256 + ((kb+tig)   ^ sw)]);
                a[mt][2] = __float_as_uint(sAc[r0*256     + ((kb+4+tig) ^ sw)]);
                a[mt][3] = __float_as_uint(sAc[(r0+8)*256 + ((kb+4+tig) ^ sw)]);
            }
            uint32_t b[4][2];
            #pragma unroll
            for (int nt = 0; nt < 4; nt++) {
                int n = ng*32 + nt*8 + gidx;
                int sn = (n & 7) << 2;
                b[nt][0] = __float_as_uint(sB[n*256 + ((kb+tig)   ^ sn)]);
                b[nt][1] = __float_as_uint(sB[n*256 + ((kb+4+tig) ^ sn)]);
            }
            #pragma unroll
            for (int mt = 0; mt < 2; mt++)
                #pragma unroll
                for (int nt = 0; nt < 4; nt++)
                    mma_tf32(c[mt][nt], a[mt], b[nt]);
        }

        // k-half 1 publishes partials
        if (kh == 1) {
            float* red = sRed + ng * 1088;   // 32 rows x stride 34
            #pragma unroll
            for (int mt = 0; mt < 2; mt++)
                #pragma unroll
                for (int nt = 0; nt < 4; nt++) {
                    int cl = nt*8 + 2*tig;
                    int r0 = mt*16 + gidx;
                    *(float2*)(red + r0*34 + cl)     = make_float2(c[mt][nt][0], c[mt][nt][1]);
                    *(float2*)(red + (r0+8)*34 + cl) = make_float2(c[mt][nt][2], c[mt][nt][3]);
                }
        }
        __syncthreads();   // sRed visible

        if (kh == 0) {
            const float* red = sRed + ng * 1088;
            int tbase = t * 32;
            #pragma unroll
            for (int mt = 0; mt < 2; mt++) {
                #pragma unroll
                for (int i2 = 0; i2 < 2; i2++) {
                    int rl = mt*16 + gidx + i2*8;
                    size_t grow = (size_t)(tbase + rl) * 128;
                    #pragma unroll
                    for (int nt = 0; nt < 4; nt++) {
                        int cl = nt*8 + 2*tig;
                        int cg = ng*32 + cl;
                        float2 pr = *(const float2*)(red + rl*34 + cl);
                        float2 bv = *(const float2*)(sbias + cg);
                        float vx = c[mt][nt][i2*2+0] + pr.x + bv.x;
                        float vy = c[mt][nt][i2*2+1] + pr.y + bv.y;
                        if (Dadd) {
                            float2 dv = *(const float2*)(Dadd + grow + cg);
                            vx += dv.x; vy += dv.y;
                        }
                        if (do_round) { vx = rnd_tf32(vx); vy = rnd_tf32(vy); }
                        *(float2*)(Y + grow + cg) = make_float2(vx, vy);
                    }
                }
            }
        }
        // next iteration's __syncthreads orders sRed reuse / sA overwrite vs this epilogue
    }
}

// ---------------- launch ----------------
extern "C" void kernel_launch(void* const* d_in, const int* in_sizes, int n_in,
                              void* d_out, int out_size) {
    const float* img  = (const float*)d_in[0];
    const float* vpos = (const float*)d_in[1];
    const float* vpad = (const float*)d_in[2];
    const int*   edges= (const int*)  d_in[3];
    const float* w0_1 = (const float*)d_in[4];
    const float* b0_1 = (const float*)d_in[5];
    const float* w1_1 = (const float*)d_in[6];
    const float* w0_2 = (const float*)d_in[7];
    const float* b0_2 = (const float*)d_in[8];
    const float* w1_2 = (const float*)d_in[9];
    const float* w0_3 = (const float*)d_in[10];
    const float* b0_3 = (const float*)d_in[11];
    const float* w1_3 = (const float*)d_in[12];
    float* out = (float*)d_out;

    float *pA, *pD, *pS, *pBt;
    cudaGetSymbolAddress((void**)&pA,  g_A);
    cudaGetSymbolAddress((void**)&pD,  g_Dk);
    cudaGetSymbolAddress((void**)&pS,  g_S);
    cudaGetSymbolAddress((void**)&pBt, g_Bt);

    const int smem = SMEM_FLOATS * sizeof(float);   // 214528 B
    cudaFuncSetAttribute(gconv_gemm, cudaFuncAttributeMaxDynamicSharedMemorySize, smem);

    int nsm = 148;
    cudaDeviceGetAttribute(&nsm, cudaDevAttrMultiProcessorCount, 0);

    // CSR build
    zero_csr<<<(Vn+255)/256, 256>>>();
    count_edges<<<(En+255)/256, 256>>>(edges);
    scan_kernel<<<1, 1024>>>();
    fill_edges<<<(En+255)/256, 256>>>(edges);

    // weights (1 launch)
    prep_weights_all<<<(6*16384)/256, 256>>>(w0_1, w1_1, w0_2, w1_2, w0_3, w1_3, pBt);

    // vert_align (output tf32-rounded)
    transpose_img<<<dim3((HWn+31)/32, Cn/32, Bn), dim3(32,32)>>>(img);
    vert_align_kernel<<<Mn/8, 256>>>(vpos, vpad);   // g_A = round(G)

    const int aggBlocks = CHUNK_ROWS / 8;   // 10000

    // conv1: D = [G|A·G] @ [W0;W1] + b0   — chunked for L2 reuse
    for (int c = 0; c < NCHUNKS; c++) {
        int row0 = c * CHUNK_ROWS, t0 = row0 / 32;
        agg_kernel<<<aggBlocks, 256>>>(pA, pS, row0);
        gconv_gemm<<<nsm, 256, smem>>>(pA, pS, pBt + 0*16384, pBt + 1*16384, b0_1,
                                       nullptr, pD, 1, t0, t0 + CTILES);
    }
    // conv2: U = [D|A·D] @ [W0;W1] + b0   (overwrites g_A)
    for (int c = 0; c < NCHUNKS; c++) {
        int row0 = c * CHUNK_ROWS, t0 = row0 / 32;
        agg_kernel<<<aggBlocks, 256>>>(pD, pS, row0);
        gconv_gemm<<<nsm, 256, smem>>>(pD, pS, pBt + 2*16384, pBt + 3*16384, b0_2,
                                       nullptr, pA, 1, t0, t0 + CTILES);
    }
    // conv3 + residual: out = D + [U|A·U] @ [W0;W1] + b0
    for (int c = 0; c < NCHUNKS; c++) {
        int row0 = c * CHUNK_ROWS, t0 = row0 / 32;
        agg_kernel<<<aggBlocks, 256>>>(pA, pS, row0);
        gconv_gemm<<<nsm, 256, smem>>>(pA, pS, pBt + 4*16384, pBt + 5*16384, b0_3,
                                       pD, out, 0, t0, t0 + CTILES);
    }
}

// round 7
// speedup vs baseline: 1.0698x; 1.0698x over previous
#include <cuda_runtime.h>
#include <cstdint>

#define Bn 16
#define Vn 40000
#define Cn 128
#define Hn 56
#define Wn 56
#define En 120000
#define Mn (Bn*Vn)          // 640000
#define HWn (Hn*Wn)         // 3136

// ---------------- device scratch ----------------
__device__ float g_imgT[(size_t)Bn*HWn*Cn];     // [B,H,W,C]
__device__ float g_A [81920000];                // G, later U (tf32-rounded)
__device__ float g_Dk[81920000];                // D (tf32-rounded; residual)
__device__ float g_T0[81920000];                // X@W0+b0
__device__ float g_T1[81920000];                // X@W1
__device__ float g_Bt[6*128*128];               // transposed tf32 weights [n][k]

__device__ int g_deg[Vn];
__device__ int g_cursor[Vn];
__device__ int g_rowptr[Vn+1];
__device__ int g_col[2*En];

// ---------------- helpers ----------------
__device__ __forceinline__ float rnd_tf32(float x) {
    float r;
    asm("cvt.rna.tf32.f32 %0, %1;" : "=f"(r) : "f"(x));
    return r;
}

__device__ __forceinline__ uint32_t smem_u32(const void* p) {
    uint32_t a;
    asm("{ .reg .u64 t; cvta.to.shared.u64 t, %1; cvt.u32.u64 %0, t; }" : "=r"(a) : "l"(p));
    return a;
}

__device__ __forceinline__ void mma_tf32(float* c, const uint32_t* a, const uint32_t* b) {
    asm volatile(
        "mma.sync.aligned.m16n8k8.row.col.f32.tf32.tf32.f32 "
        "{%0,%1,%2,%3}, {%4,%5,%6,%7}, {%8,%9}, {%0,%1,%2,%3};"
        : "+f"(c[0]), "+f"(c[1]), "+f"(c[2]), "+f"(c[3])
        : "r"(a[0]), "r"(a[1]), "r"(a[2]), "r"(a[3]), "r"(b[0]), "r"(b[1]));
}

// ---------------- CSR build ----------------
__global__ void zero_csr() {
    int i = blockIdx.x*blockDim.x + threadIdx.x;
    if (i < Vn) { g_deg[i] = 0; g_cursor[i] = 0; }
}

__global__ void count_edges(const int* __restrict__ edges) {
    int e = blockIdx.x*blockDim.x + threadIdx.x;
    if (e < En) {
        atomicAdd(&g_deg[edges[2*e+0]], 1);
        atomicAdd(&g_deg[edges[2*e+1]], 1);
    }
}

__global__ void scan_kernel() {
    __shared__ int partial[1024];
    int t = threadIdx.x;
    const int CH = (Vn + 1023) / 1024;
    int base = t * CH;
    int s = 0;
    for (int i = 0; i < CH; i++) {
        int idx = base + i;
        if (idx < Vn) s += g_deg[idx];
    }
    partial[t] = s;
    __syncthreads();
    for (int off = 1; off < 1024; off <<= 1) {
        int v = 0;
        if (t >= off) v = partial[t - off];
        __syncthreads();
        partial[t] += v;
        __syncthreads();
    }
    int run = (t == 0) ? 0 : partial[t-1];
    for (int i = 0; i < CH; i++) {
        int idx = base + i;
        if (idx < Vn) { g_rowptr[idx] = run; run += g_deg[idx]; }
    }
    if (t == 1023) g_rowptr[Vn] = run;
}

__global__ void fill_edges(const int* __restrict__ edges) {
    int e = blockIdx.x*blockDim.x + threadIdx.x;
    if (e < En) {
        int i = edges[2*e+0], j = edges[2*e+1];
        int p = atomicAdd(&g_cursor[i], 1);
        g_col[g_rowptr[i] + p] = j;
        int q = atomicAdd(&g_cursor[j], 1);
        g_col[g_rowptr[j] + q] = i;
    }
}

// ---------------- weight prep: all 6 matrices in one launch ----------------
__global__ void prep_weights_all(const float* __restrict__ W0_1, const float* __restrict__ W1_1,
                                 const float* __restrict__ W0_2, const float* __restrict__ W1_2,
                                 const float* __restrict__ W0_3, const float* __restrict__ W1_3,
                                 float* __restrict__ Bt) {
    int i = blockIdx.x*blockDim.x + threadIdx.x;   // 6*16384
    int m = i >> 14;
    int r = i & 16383;
    int n = r >> 7, k = r & 127;
    const float* W = (m == 0) ? W0_1 : (m == 1) ? W1_1 : (m == 2) ? W0_2 :
                     (m == 3) ? W1_2 : (m == 4) ? W0_3 : W1_3;
    Bt[i] = rnd_tf32(W[k*128 + n]);
}

// ---------------- image transpose [B,C,H,W] -> [B,H,W,C] ----------------
__global__ void transpose_img(const float* __restrict__ img) {
    __shared__ float tile[32][33];
    int b   = blockIdx.z;
    int hw0 = blockIdx.x * 32;
    int c0  = blockIdx.y * 32;
    int tx = threadIdx.x, ty = threadIdx.y;
    int hw = hw0 + tx, c = c0 + ty;
    if (hw < HWn)
        tile[ty][tx] = img[((size_t)(b*Cn + c))*HWn + hw];
    __syncthreads();
    int hw2 = hw0 + ty, c2 = c0 + tx;
    if (hw2 < HWn)
        g_imgT[((size_t)(b*HWn + hw2))*Cn + c2] = tile[tx][ty];
}

// ---------------- vert_align + add padded -> g_A (tf32-rounded) ----------------
__global__ void vert_align_kernel(const float* __restrict__ vpos,
                                  const float* __restrict__ vpad) {
    int gw   = (blockIdx.x*blockDim.x + threadIdx.x) >> 5;
    int lane = threadIdx.x & 31;
    if (gw >= Mn) return;
    int b = gw / Vn;

    float px = vpos[(size_t)gw*3 + 0];
    float py = vpos[(size_t)gw*3 + 1];
    float x = (px + 1.0f) * 0.5f * (float)(Wn - 1);
    float y = (py + 1.0f) * 0.5f * (float)(Hn - 1);
    float x0f = floorf(x), y0f = floorf(y);
    float wx1 = x - x0f, wx0 = 1.0f - wx1;
    float wy1 = y - y0f, wy0 = 1.0f - wy1;
    int x0 = (int)x0f, y0 = (int)y0f;

    float4 acc = ((const float4*)(vpad + (size_t)gw*Cn))[lane];

    int   xs_[4] = { x0, x0+1, x0,   x0+1 };
    int   ys_[4] = { y0, y0,   y0+1, y0+1 };
    float ws_[4] = { wx0*wy0, wx1*wy0, wx0*wy1, wx1*wy1 };

    #pragma unroll
    for (int t = 0; t < 4; t++) {
        int xi = xs_[t], yi = ys_[t];
        bool inb = (xi >= 0) && (xi < Wn) && (yi >= 0) && (yi < Hn);
        float wgt = inb ? ws_[t] : 0.0f;
        if (wgt != 0.0f) {
            float4 f = ((const float4*)(g_imgT + ((size_t)((b*Hn + yi)*Wn + xi))*Cn))[lane];
            acc.x += wgt*f.x; acc.y += wgt*f.y; acc.z += wgt*f.z; acc.w += wgt*f.w;
        }
    }
    acc.x = rnd_tf32(acc.x); acc.y = rnd_tf32(acc.y);
    acc.z = rnd_tf32(acc.z); acc.w = rnd_tf32(acc.w);
    ((float4*)(g_A + (size_t)gw*Cn))[lane] = acc;
}

// ---------------- tf32 mma.sync dual GEMM: Y0 = X@W0+b0, Y1 = X@W1 ----------------
// (identical to R3's proven kernel)
#define TILE_M 64
#define SMEM_FLOATS (32768 + 16384 + 128)

__device__ __forceinline__ void issue_tile(const float* __restrict__ X, int t, int buf,
                                           int tid, uint32_t sA_u) {
    const float* src0 = X + (size_t)t * (TILE_M * 128);
    uint32_t dbase = sA_u + (uint32_t)buf * 32768u;   // bytes
    #pragma unroll
    for (int j = 0; j < 8; j++) {
        int i4 = tid + j*256;            // 0..2047 float4s
        int row = i4 >> 5;
        int kq  = (i4 & 31) << 2;
        uint32_t off = (uint32_t)((row << 7) + (kq ^ ((row & 7) << 2))) * 4u;
        asm volatile("cp.async.cg.shared.global [%0], [%1], 16;"
            :: "r"(dbase + off), "l"(src0 + row*128 + kq));
    }
    asm volatile("cp.async.commit_group;" ::: "memory");
}

__global__ void __launch_bounds__(256, 1)
gemm_dual_mma(const float* __restrict__ X,
              const float* __restrict__ Bt0, const float* __restrict__ Bt1,
              const float* __restrict__ bias,
              float* __restrict__ Y0, float* __restrict__ Y1) {
    extern __shared__ float smf[];
    float* sB    = smf;            // 32768 floats
    float* sA    = smf + 32768;    // 16384 floats (2 stages of 8192)
    float* sbias = smf + 49152;    // 128 floats

    int tid = threadIdx.x;

    for (int i4 = tid; i4 < 8192; i4 += 256) {
        int n  = i4 >> 5;
        int kq = (i4 & 31) << 2;
        const float* src = (n < 128) ? (Bt0 + n*128 + kq) : (Bt1 + (n-128)*128 + kq);
        float4 v = *(const float4*)src;
        *(float4*)(sB + n*128 + (kq ^ ((n & 7) << 2))) = v;
    }
    if (tid < 128) sbias[tid] = bias[tid];

    uint32_t sA_u = smem_u32(sA);

    int wid = tid >> 5, lane = tid & 31;
    int gidx = lane >> 2, tig = lane & 3;
    int rowg = wid & 1, colg = wid >> 1;       // 2 row groups x 4 col groups
    int m0w = rowg * 32;
    int colbase = colg * 64;                    // 0..255 (128..255 -> Y1)
    const uint32_t xsw = (uint32_t)(gidx << 2);

    const int ntot = Mn / TILE_M;               // 10000
    const int grid = gridDim.x;

    int t = blockIdx.x;
    if (t < ntot) issue_tile(X, t, 0, tid, sA_u);

    int it = 0;
    for (; t < ntot; t += grid, it++) {
        int tn = t + grid;
        if (tn < ntot) {
            issue_tile(X, tn, (it + 1) & 1, tid, sA_u);
            asm volatile("cp.async.wait_group 1;" ::: "memory");
        } else {
            asm volatile("cp.async.wait_group 0;" ::: "memory");
        }
        __syncthreads();

        const float* sAb = sA + (it & 1) * 8192;

        float c[2][8][4];
        #pragma unroll
        for (int mt = 0; mt < 2; mt++)
            #pragma unroll
            for (int nt = 0; nt < 8; nt++)
                #pragma unroll
                for (int q = 0; q < 4; q++) c[mt][nt][q] = 0.0f;

        #pragma unroll 4
        for (int ks = 0; ks < 16; ks++) {
            int kb = ks * 8;
            uint32_t ka0 = (uint32_t)(kb + tig)     ^ xsw;
            uint32_t ka1 = (uint32_t)(kb + 4 + tig) ^ xsw;

            uint32_t a[2][4];
            #pragma unroll
            for (int mt = 0; mt < 2; mt++) {
                int r0 = m0w + mt*16 + gidx;
                int r1 = r0 + 8;
                a[mt][0] = __float_as_uint(sAb[r0*128 + ka0]);
                a[mt][1] = __float_as_uint(sAb[r1*128 + ka0]);
                a[mt][2] = __float_as_uint(sAb[r0*128 + ka1]);
                a[mt][3] = __float_as_uint(sAb[r1*128 + ka1]);
            }
            uint32_t b[8][2];
            #pragma unroll
            for (int nt = 0; nt < 8; nt++) {
                int n = colbase + nt*8 + gidx;
                b[nt][0] = __float_as_uint(sB[n*128 + ka0]);
                b[nt][1] = __float_as_uint(sB[n*128 + ka1]);
            }
            #pragma unroll
            for (int mt = 0; mt < 2; mt++)
                #pragma unroll
                for (int nt = 0; nt < 8; nt++)
                    mma_tf32(c[mt][nt], a[mt], b[nt]);
        }

        int rowbase = t * TILE_M + m0w + gidx;
        #pragma unroll
        for (int mt = 0; mt < 2; mt++) {
            int row = rowbase + mt*16;
            #pragma unroll
            for (int nt = 0; nt < 8; nt++) {
                int col = colbase + nt*8 + 2*tig;
                float v0 = c[mt][nt][0], v1 = c[mt][nt][1];
                float v2 = c[mt][nt][2], v3 = c[mt][nt][3];
                if (colg < 2) {
                    float bv0 = sbias[col], bv1 = sbias[col + 1];
                    *(float2*)(Y0 + (size_t)row*128 + col)     = make_float2(v0 + bv0, v1 + bv1);
                    *(float2*)(Y0 + (size_t)(row+8)*128 + col) = make_float2(v2 + bv0, v3 + bv1);
                } else {
                    int c1 = col - 128;
                    *(float2*)(Y1 + (size_t)row*128 + c1)      = make_float2(v0, v1);
                    *(float2*)(Y1 + (size_t)(row+8)*128 + c1)  = make_float2(v2, v3);
                }
            }
        }
        __syncthreads();
    }
}

// ---------------- combine (MLP-batched gather): out = T0 (+Dadd) + sum_{j in N(v)} T1[b,j] ----------------
__global__ void combine_kernel(const float* __restrict__ T0,
                               const float* __restrict__ T1,
                               const float* __restrict__ Dadd,
                               float* __restrict__ outp,
                               int do_round) {
    int gw   = (blockIdx.x*blockDim.x + threadIdx.x) >> 5;
    int lane = threadIdx.x & 31;
    if (gw >= Mn) return;
    int b = gw / Vn;
    int v = gw - b*Vn;

    size_t off = (size_t)gw*Cn + lane*4;
    float4 acc = *(const float4*)(T0 + off);
    if (Dadd) {
        float4 d = *(const float4*)(Dadd + off);
        acc.x += d.x; acc.y += d.y; acc.z += d.z; acc.w += d.w;
    }

    int s = g_rowptr[v];
    int e = g_rowptr[v+1];
    const float* baseT1 = T1 + (size_t)b*Vn*Cn + lane*4;

    int p = s;
    // full batches of 8: indices first, then 8 row loads in flight, then accumulate
    while (p + 8 <= e) {
        int jj[8];
        #pragma unroll
        for (int q = 0; q < 8; q++) jj[q] = __ldg(&g_col[p + q]);
        float4 f[8];
        #pragma unroll
        for (int q = 0; q < 8; q++) f[q] = *(const float4*)(baseT1 + (size_t)jj[q]*Cn);
        #pragma unroll
        for (int q = 0; q < 8; q++) {
            acc.x += f[q].x; acc.y += f[q].y; acc.z += f[q].z; acc.w += f[q].w;
        }
        p += 8;
    }
    // tail (0..7), predicated — loads still issued back-to-back
    {
        int rem = e - p;
        int jj[8];
        #pragma unroll
        for (int q = 0; q < 8; q++) jj[q] = (q < rem) ? __ldg(&g_col[p + q]) : 0;
        float4 f[8];
        #pragma unroll
        for (int q = 0; q < 8; q++)
            if (q < rem) f[q] = *(const float4*)(baseT1 + (size_t)jj[q]*Cn);
        #pragma unroll
        for (int q = 0; q < 8; q++)
            if (q < rem) {
                acc.x += f[q].x; acc.y += f[q].y; acc.z += f[q].z; acc.w += f[q].w;
            }
    }

    if (do_round) {
        acc.x = rnd_tf32(acc.x); acc.y = rnd_tf32(acc.y);
        acc.z = rnd_tf32(acc.z); acc.w = rnd_tf32(acc.w);
    }
    *(float4*)(outp + off) = acc;
}

// ---------------- launch ----------------
extern "C" void kernel_launch(void* const* d_in, const int* in_sizes, int n_in,
                              void* d_out, int out_size) {
    const float* img  = (const float*)d_in[0];
    const float* vpos = (const float*)d_in[1];
    const float* vpad = (const float*)d_in[2];
    const int*   edges= (const int*)  d_in[3];
    const float* w0_1 = (const float*)d_in[4];
    const float* b0_1 = (const float*)d_in[5];
    const float* w1_1 = (const float*)d_in[6];
    const float* w0_2 = (const float*)d_in[7];
    const float* b0_2 = (const float*)d_in[8];
    const float* w1_2 = (const float*)d_in[9];
    const float* w0_3 = (const float*)d_in[10];
    const float* b0_3 = (const float*)d_in[11];
    const float* w1_3 = (const float*)d_in[12];
    float* out = (float*)d_out;

    float *pA, *pD, *pT0, *pT1, *pBt;
    cudaGetSymbolAddress((void**)&pA,  g_A);
    cudaGetSymbolAddress((void**)&pD,  g_Dk);
    cudaGetSymbolAddress((void**)&pT0, g_T0);
    cudaGetSymbolAddress((void**)&pT1, g_T1);
    cudaGetSymbolAddress((void**)&pBt, g_Bt);

    const int smem = SMEM_FLOATS * sizeof(float);   // 197120 B
    cudaFuncSetAttribute(gemm_dual_mma, cudaFuncAttributeMaxDynamicSharedMemorySize, smem);

    int nsm = 148;
    cudaDeviceGetAttribute(&nsm, cudaDevAttrMultiProcessorCount, 0);

    // CSR build
    zero_csr<<<(Vn+255)/256, 256>>>();
    count_edges<<<(En+255)/256, 256>>>(edges);
    scan_kernel<<<1, 1024>>>();
    fill_edges<<<(En+255)/256, 256>>>(edges);

    // weights (single launch)
    prep_weights_all<<<(6*16384)/256, 256>>>(w0_1, w1_1, w0_2, w1_2, w0_3, w1_3, pBt);

    // vert_align
    transpose_img<<<dim3((HWn+31)/32, Cn/32, Bn), dim3(32,32)>>>(img);
    vert_align_kernel<<<Mn/8, 256>>>(vpos, vpad);   // g_A = round(G)

    // conv1: D = G@W0+b0 + agg(G@W1)
    gemm_dual_mma<<<nsm, 256, smem>>>(pA, pBt + 0*16384, pBt + 1*16384, b0_1, pT0, pT1);
    combine_kernel<<<Mn/8, 256>>>(pT0, pT1, nullptr, pD, 1);

    // conv2: U = D@W0+b0 + agg(D@W1)
    gemm_dual_mma<<<nsm, 256, smem>>>(pD, pBt + 2*16384, pBt + 3*16384, b0_2, pT0, pT1);
    combine_kernel<<<Mn/8, 256>>>(pT0, pT1, nullptr, pA, 1);

    // conv3 + final residual: out = D + (U@W0+b0 + agg(U@W1))
    gemm_dual_mma<<<nsm, 256, smem>>>(pA, pBt + 4*16384, pBt + 5*16384, b0_3, pT0, pT1);
    combine_kernel<<<Mn/8, 256>>>(pT0, pT1, pD, out, 0);
}

// round 8
// speedup vs baseline: 1.3109x; 1.2254x over previous
#include <cuda_runtime.h>
#include <cstdint>

#define Bn 16
#define Vn 40000
#define Cn 128
#define Hn 56
#define Wn 56
#define En 120000
#define Mn (Bn*Vn)          // 640000
#define HWn (Hn*Wn)         // 3136

// ---------------- device scratch ----------------
__device__ float g_imgT[(size_t)Bn*HWn*Cn];     // [B,H,W,C]
__device__ float g_A [81920000];                // G, later U (tf32-rounded)
__device__ float g_Dk[81920000];                // D (tf32-rounded; residual)
__device__ float g_T0[81920000];                // X@W0+b0
__device__ float g_T1[81920000];                // X@W1
__device__ float g_Bt[6*128*128];               // transposed tf32 weights [n][k]

__device__ int g_deg[Vn];
__device__ int g_cursor[Vn];
__device__ int g_rowptr[Vn+1];
__device__ int g_col[2*En];

// ---------------- helpers ----------------
__device__ __forceinline__ float rnd_tf32(float x) {
    float r;
    asm("cvt.rna.tf32.f32 %0, %1;" : "=f"(r) : "f"(x));
    return r;
}

__device__ __forceinline__ uint32_t smem_u32(const void* p) {
    uint32_t a;
    asm("{ .reg .u64 t; cvta.to.shared.u64 t, %1; cvt.u32.u64 %0, t; }" : "=r"(a) : "l"(p));
    return a;
}

__device__ __forceinline__ void mma_tf32(float* c, const uint32_t* a, const uint32_t* b) {
    asm volatile(
        "mma.sync.aligned.m16n8k8.row.col.f32.tf32.tf32.f32 "
        "{%0,%1,%2,%3}, {%4,%5,%6,%7}, {%8,%9}, {%0,%1,%2,%3};"
        : "+f"(c[0]), "+f"(c[1]), "+f"(c[2]), "+f"(c[3])
        : "r"(a[0]), "r"(a[1]), "r"(a[2]), "r"(a[3]), "r"(b[0]), "r"(b[1]));
}

// ---------------- CSR build ----------------
__global__ void zero_csr() {
    int i = blockIdx.x*blockDim.x + threadIdx.x;
    if (i < Vn) { g_deg[i] = 0; g_cursor[i] = 0; }
}

__global__ void count_edges(const int* __restrict__ edges) {
    int e = blockIdx.x*blockDim.x + threadIdx.x;
    if (e < En) {
        atomicAdd(&g_deg[edges[2*e+0]], 1);
        atomicAdd(&g_deg[edges[2*e+1]], 1);
    }
}

__global__ void scan_kernel() {
    __shared__ int partial[1024];
    int t = threadIdx.x;
    const int CH = (Vn + 1023) / 1024;
    int base = t * CH;
    int s = 0;
    for (int i = 0; i < CH; i++) {
        int idx = base + i;
        if (idx < Vn) s += g_deg[idx];
    }
    partial[t] = s;
    __syncthreads();
    for (int off = 1; off < 1024; off <<= 1) {
        int v = 0;
        if (t >= off) v = partial[t - off];
        __syncthreads();
        partial[t] += v;
        __syncthreads();
    }
    int run = (t == 0) ? 0 : partial[t-1];
    for (int i = 0; i < CH; i++) {
        int idx = base + i;
        if (idx < Vn) { g_rowptr[idx] = run; run += g_deg[idx]; }
    }
    if (t == 1023) g_rowptr[Vn] = run;
}

__global__ void fill_edges(const int* __restrict__ edges) {
    int e = blockIdx.x*blockDim.x + threadIdx.x;
    if (e < En) {
        int i = edges[2*e+0], j = edges[2*e+1];
        int p = atomicAdd(&g_cursor[i], 1);
        g_col[g_rowptr[i] + p] = j;
        int q = atomicAdd(&g_cursor[j], 1);
        g_col[g_rowptr[j] + q] = i;
    }
}

// ---------------- weight prep: all 6 matrices in one launch ----------------
__global__ void prep_weights_all(const float* __restrict__ W0_1, const float* __restrict__ W1_1,
                                 const float* __restrict__ W0_2, const float* __restrict__ W1_2,
                                 const float* __restrict__ W0_3, const float* __restrict__ W1_3,
                                 float* __restrict__ Bt) {
    int i = blockIdx.x*blockDim.x + threadIdx.x;   // 6*16384
    int m = i >> 14;
    int r = i & 16383;
    int n = r >> 7, k = r & 127;
    const float* W = (m == 0) ? W0_1 : (m == 1) ? W1_1 : (m == 2) ? W0_2 :
                     (m == 3) ? W1_2 : (m == 4) ? W0_3 : W1_3;
    Bt[i] = rnd_tf32(W[k*128 + n]);
}

// ---------------- image transpose [B,C,H,W] -> [B,H,W,C] ----------------
__global__ void transpose_img(const float* __restrict__ img) {
    __shared__ float tile[32][33];
    int b   = blockIdx.z;
    int hw0 = blockIdx.x * 32;
    int c0  = blockIdx.y * 32;
    int tx = threadIdx.x, ty = threadIdx.y;
    int hw = hw0 + tx, c = c0 + ty;
    if (hw < HWn)
        tile[ty][tx] = img[((size_t)(b*Cn + c))*HWn + hw];
    __syncthreads();
    int hw2 = hw0 + ty, c2 = c0 + tx;
    if (hw2 < HWn)
        g_imgT[((size_t)(b*HWn + hw2))*Cn + c2] = tile[tx][ty];
}

// ---------------- vert_align + add padded -> g_A (tf32-rounded) ----------------
__global__ void vert_align_kernel(const float* __restrict__ vpos,
                                  const float* __restrict__ vpad) {
    int gw   = (blockIdx.x*blockDim.x + threadIdx.x) >> 5;
    int lane = threadIdx.x & 31;
    if (gw >= Mn) return;
    int b = gw / Vn;

    float px = vpos[(size_t)gw*3 + 0];
    float py = vpos[(size_t)gw*3 + 1];
    float x = (px + 1.0f) * 0.5f * (float)(Wn - 1);
    float y = (py + 1.0f) * 0.5f * (float)(Hn - 1);
    float x0f = floorf(x), y0f = floorf(y);
    float wx1 = x - x0f, wx0 = 1.0f - wx1;
    float wy1 = y - y0f, wy0 = 1.0f - wy1;
    int x0 = (int)x0f, y0 = (int)y0f;

    float4 acc = ((const float4*)(vpad + (size_t)gw*Cn))[lane];

    int   xs_[4] = { x0, x0+1, x0,   x0+1 };
    int   ys_[4] = { y0, y0,   y0+1, y0+1 };
    float ws_[4] = { wx0*wy0, wx1*wy0, wx0*wy1, wx1*wy1 };

    #pragma unroll
    for (int t = 0; t < 4; t++) {
        int xi = xs_[t], yi = ys_[t];
        bool inb = (xi >= 0) && (xi < Wn) && (yi >= 0) && (yi < Hn);
        float wgt = inb ? ws_[t] : 0.0f;
        if (wgt != 0.0f) {
            float4 f = ((const float4*)(g_imgT + ((size_t)((b*Hn + yi)*Wn + xi))*Cn))[lane];
            acc.x += wgt*f.x; acc.y += wgt*f.y; acc.z += wgt*f.z; acc.w += wgt*f.w;
        }
    }
    acc.x = rnd_tf32(acc.x); acc.y = rnd_tf32(acc.y);
    acc.z = rnd_tf32(acc.z); acc.w = rnd_tf32(acc.w);
    ((float4*)(g_A + (size_t)gw*Cn))[lane] = acc;
}

// ---------------- tf32 mma.sync dual GEMM: Y0 = X@W0+b0, Y1 = X@W1 ----------------
#define TILE_M 64
#define SMEM_FLOATS (32768 + 16384 + 128)

__device__ __forceinline__ void issue_tile(const float* __restrict__ X, int t, int buf,
                                           int tid, uint32_t sA_u) {
    const float* src0 = X + (size_t)t * (TILE_M * 128);
    uint32_t dbase = sA_u + (uint32_t)buf * 32768u;   // bytes
    #pragma unroll
    for (int j = 0; j < 8; j++) {
        int i4 = tid + j*256;            // 0..2047 float4s
        int row = i4 >> 5;
        int kq  = (i4 & 31) << 2;
        uint32_t off = (uint32_t)((row << 7) + (kq ^ ((row & 7) << 2))) * 4u;
        asm volatile("cp.async.cg.shared.global [%0], [%1], 16;"
            :: "r"(dbase + off), "l"(src0 + row*128 + kq));
    }
    asm volatile("cp.async.commit_group;" ::: "memory");
}

__global__ void __launch_bounds__(256, 1)
gemm_dual_mma(const float* __restrict__ X,
              const float* __restrict__ Bt0, const float* __restrict__ Bt1,
              const float* __restrict__ bias,
              float* __restrict__ Y0, float* __restrict__ Y1) {
    extern __shared__ float smf[];
    float* sB    = smf;            // 32768 floats
    float* sA    = smf + 32768;    // 16384 floats (2 stages of 8192)
    float* sbias = smf + 49152;    // 128 floats

    int tid = threadIdx.x;

    for (int i4 = tid; i4 < 8192; i4 += 256) {
        int n  = i4 >> 5;
        int kq = (i4 & 31) << 2;
        const float* src = (n < 128) ? (Bt0 + n*128 + kq) : (Bt1 + (n-128)*128 + kq);
        float4 v = *(const float4*)src;
        *(float4*)(sB + n*128 + (kq ^ ((n & 7) << 2))) = v;
    }
    if (tid < 128) sbias[tid] = bias[tid];

    uint32_t sA_u = smem_u32(sA);

    int wid = tid >> 5, lane = tid & 31;
    int gidx = lane >> 2, tig = lane & 3;
    int rowg = wid & 1, colg = wid >> 1;       // 2 row groups x 4 col groups
    int m0w = rowg * 32;
    int colbase = colg * 64;                    // 0..255 (128..255 -> Y1)
    const uint32_t xsw = (uint32_t)(gidx << 2);

    const int ntot = Mn / TILE_M;               // 10000
    const int grid = gridDim.x;

    int t = blockIdx.x;
    if (t < ntot) issue_tile(X, t, 0, tid, sA_u);

    int it = 0;
    for (; t < ntot; t += grid, it++) {
        int tn = t + grid;
        if (tn < ntot) {
            issue_tile(X, tn, (it + 1) & 1, tid, sA_u);
            asm volatile("cp.async.wait_group 1;" ::: "memory");
        } else {
            asm volatile("cp.async.wait_group 0;" ::: "memory");
        }
        __syncthreads();

        const float* sAb = sA + (it & 1) * 8192;

        float c[2][8][4];
        #pragma unroll
        for (int mt = 0; mt < 2; mt++)
            #pragma unroll
            for (int nt = 0; nt < 8; nt++)
                #pragma unroll
                for (int q = 0; q < 4; q++) c[mt][nt][q] = 0.0f;

        // fragment double-buffered k-loop (ping-pong on ks&1, full unroll)
        uint32_t af[2][2][4], bf[2][8][2];
        {
            // preload kstep 0
            uint32_t ka0 = (uint32_t)(0 + tig)     ^ xsw;
            uint32_t ka1 = (uint32_t)(0 + 4 + tig) ^ xsw;
            #pragma unroll
            for (int mt = 0; mt < 2; mt++) {
                int r0 = m0w + mt*16 + gidx;
                int r1 = r0 + 8;
                af[0][mt][0] = __float_as_uint(sAb[r0*128 + ka0]);
                af[0][mt][1] = __float_as_uint(sAb[r1*128 + ka0]);
                af[0][mt][2] = __float_as_uint(sAb[r0*128 + ka1]);
                af[0][mt][3] = __float_as_uint(sAb[r1*128 + ka1]);
            }
            #pragma unroll
            for (int nt = 0; nt < 8; nt++) {
                int n = colbase + nt*8 + gidx;
                bf[0][nt][0] = __float_as_uint(sB[n*128 + ka0]);
                bf[0][nt][1] = __float_as_uint(sB[n*128 + ka1]);
            }
        }
        #pragma unroll
        for (int ks = 0; ks < 16; ks++) {
            int cur = ks & 1, nxt = cur ^ 1;
            if (ks < 15) {
                int kb = (ks + 1) * 8;
                uint32_t ka0 = (uint32_t)(kb + tig)     ^ xsw;
                uint32_t ka1 = (uint32_t)(kb + 4 + tig) ^ xsw;
                #pragma unroll
                for (int mt = 0; mt < 2; mt++) {
                    int r0 = m0w + mt*16 + gidx;
                    int r1 = r0 + 8;
                    af[nxt][mt][0] = __float_as_uint(sAb[r0*128 + ka0]);
                    af[nxt][mt][1] = __float_as_uint(sAb[r1*128 + ka0]);
                    af[nxt][mt][2] = __float_as_uint(sAb[r0*128 + ka1]);
                    af[nxt][mt][3] = __float_as_uint(sAb[r1*128 + ka1]);
                }
                #pragma unroll
                for (int nt = 0; nt < 8; nt++) {
                    int n = colbase + nt*8 + gidx;
                    bf[nxt][nt][0] = __float_as_uint(sB[n*128 + ka0]);
                    bf[nxt][nt][1] = __float_as_uint(sB[n*128 + ka1]);
                }
            }
            #pragma unroll
            for (int mt = 0; mt < 2; mt++)
                #pragma unroll
                for (int nt = 0; nt < 8; nt++)
                    mma_tf32(c[mt][nt], af[cur][mt], bf[cur][nt]);
        }

        int rowbase = t * TILE_M + m0w + gidx;
        #pragma unroll
        for (int mt = 0; mt < 2; mt++) {
            int row = rowbase + mt*16;
            #pragma unroll
            for (int nt = 0; nt < 8; nt++) {
                int col = colbase + nt*8 + 2*tig;
                float v0 = c[mt][nt][0], v1 = c[mt][nt][1];
                float v2 = c[mt][nt][2], v3 = c[mt][nt][3];
                if (colg < 2) {
                    float bv0 = sbias[col], bv1 = sbias[col + 1];
                    *(float2*)(Y0 + (size_t)row*128 + col)     = make_float2(v0 + bv0, v1 + bv1);
                    *(float2*)(Y0 + (size_t)(row+8)*128 + col) = make_float2(v2 + bv0, v3 + bv1);
                } else {
                    int c1 = col - 128;
                    *(float2*)(Y1 + (size_t)row*128 + c1)      = make_float2(v0, v1);
                    *(float2*)(Y1 + (size_t)(row+8)*128 + c1)  = make_float2(v2, v3);
                }
            }
        }
        __syncthreads();
    }
}

// ---------------- combine (R3 exact): out = T0 (+Dadd) + sum_{j in N(v)} T1[b,j] ----------------
__global__ void combine_kernel(const float* __restrict__ T0,
                               const float* __restrict__ T1,
                               const float* __restrict__ Dadd,
                               float* __restrict__ outp,
                               int do_round) {
    int gw   = (blockIdx.x*blockDim.x + threadIdx.x) >> 5;
    int lane = threadIdx.x & 31;
    if (gw >= Mn) return;
    int b = gw / Vn;
    int v = gw - b*Vn;

    size_t off = (size_t)gw*Cn + lane*4;
    float4 acc = *(const float4*)(T0 + off);
    if (Dadd) {
        float4 d = *(const float4*)(Dadd + off);
        acc.x += d.x; acc.y += d.y; acc.z += d.z; acc.w += d.w;
    }
    int s = g_rowptr[v];
    int e = g_rowptr[v+1];
    const float* baseT1 = T1 + (size_t)b*Vn*Cn + lane*4;
    for (int p = s; p < e; p++) {
        int j = __ldg(&g_col[p]);
        float4 t = *(const float4*)(baseT1 + (size_t)j*Cn);
        acc.x += t.x; acc.y += t.y; acc.z += t.z; acc.w += t.w;
    }
    if (do_round) {
        acc.x = rnd_tf32(acc.x); acc.y = rnd_tf32(acc.y);
        acc.z = rnd_tf32(acc.z); acc.w = rnd_tf32(acc.w);
    }
    *(float4*)(outp + off) = acc;
}

// ---------------- launch ----------------
extern "C" void kernel_launch(void* const* d_in, const int* in_sizes, int n_in,
                              void* d_out, int out_size) {
    const float* img  = (const float*)d_in[0];
    const float* vpos = (const float*)d_in[1];
    const float* vpad = (const float*)d_in[2];
    const int*   edges= (const int*)  d_in[3];
    const float* w0_1 = (const float*)d_in[4];
    const float* b0_1 = (const float*)d_in[5];
    const float* w1_1 = (const float*)d_in[6];
    const float* w0_2 = (const float*)d_in[7];
    const float* b0_2 = (const float*)d_in[8];
    const float* w1_2 = (const float*)d_in[9];
    const float* w0_3 = (const float*)d_in[10];
    const float* b0_3 = (const float*)d_in[11];
    const float* w1_3 = (const float*)d_in[12];
    float* out = (float*)d_out;

    float *pA, *pD, *pT0, *pT1, *pBt;
    cudaGetSymbolAddress((void**)&pA,  g_A);
    cudaGetSymbolAddress((void**)&pD,  g_Dk);
    cudaGetSymbolAddress((void**)&pT0, g_T0);
    cudaGetSymbolAddress((void**)&pT1, g_T1);
    cudaGetSymbolAddress((void**)&pBt, g_Bt);

    const int smem = SMEM_FLOATS * sizeof(float);   // 197120 B
    cudaFuncSetAttribute(gemm_dual_mma, cudaFuncAttributeMaxDynamicSharedMemorySize, smem);

    int nsm = 148;
    cudaDeviceGetAttribute(&nsm, cudaDevAttrMultiProcessorCount, 0);

    // 1: weights  2: transpose  3: vert_align  4: gemm1  (gemm1 lands in the ncu slot)
    prep_weights_all<<<(6*16384)/256, 256>>>(w0_1, w1_1, w0_2, w1_2, w0_3, w1_3, pBt);
    transpose_img<<<dim3((HWn+31)/32, Cn/32, Bn), dim3(32,32)>>>(img);
    vert_align_kernel<<<Mn/8, 256>>>(vpos, vpad);   // g_A = round(G)
    gemm_dual_mma<<<nsm, 256, smem>>>(pA, pBt + 0*16384, pBt + 1*16384, b0_1, pT0, pT1);

    // CSR build (needed only before combine1; runs while gemm1 results settle)
    zero_csr<<<(Vn+255)/256, 256>>>();
    count_edges<<<(En+255)/256, 256>>>(edges);
    scan_kernel<<<1, 1024>>>();
    fill_edges<<<(En+255)/256, 256>>>(edges);

    // conv1: D = G@W0+b0 + agg(G@W1)
    combine_kernel<<<Mn/8, 256>>>(pT0, pT1, nullptr, pD, 1);

    // conv2: U = D@W0+b0 + agg(D@W1)
    gemm_dual_mma<<<nsm, 256, smem>>>(pD, pBt + 2*16384, pBt + 3*16384, b0_2, pT0, pT1);
    combine_kernel<<<Mn/8, 256>>>(pT0, pT1, nullptr, pA, 1);

    // conv3 + final residual: out = D + (U@W0+b0 + agg(U@W1))
    gemm_dual_mma<<<nsm, 256, smem>>>(pA, pBt + 4*16384, pBt + 5*16384, b0_3, pT0, pT1);
    combine_kernel<<<Mn/8, 256>>>(pT0, pT1, pD, out, 0);
}